// round 15
// baseline (speedup 1.0000x reference)
#include <cuda_runtime.h>
#include <cuda_bf16.h>
#include <cuda_fp16.h>
#include <math.h>
#include <stdint.h>

#define BATCH 8
#define LQ 2048
#define LK 2048
#define DIM 640
#define INV_TEMP (1.0f / 13.0f)

// ---------------------------------------------------------------------------
// Device scratch (allocation-free rule: __device__ globals)
// GEMM1 operands (fp16 merged split, e = 2^-10):
//   row layout [hi(0:DIM) | mid(DIM:2*DIM)]
// GEMM2 operands: plain fp16 (attn, v^T)
// ---------------------------------------------------------------------------
__device__ float g_qq[BATCH * LQ];
__device__ float g_kk[BATCH * LK];
__device__ __half g_qcat[(size_t)BATCH * LQ * 2 * DIM];   // [B*LQ, 1280]
__device__ __half g_kcat[(size_t)BATCH * LK * 2 * DIM];   // [B*LK, 1280]
__device__ __half g_v16[(size_t)BATCH * DIM * LK];        // [B*DIM, 2048] (v^T fp16)
__device__ __half g_a16[(size_t)BATCH * LQ * LK];         // [B*LQ, 2048] (attn fp16)

// ---------------------------------------------------------------------------
// helpers
// ---------------------------------------------------------------------------
__device__ __forceinline__ uint32_t smem_u32(const void* p) {
    uint32_t a;
    asm("{ .reg .u64 t; cvta.to.shared.u64 t, %1; cvt.u32.u64 %0, t; }" : "=r"(a) : "l"(p));
    return a;
}
__device__ __forceinline__ void cp16(uint32_t dst, const void* src) {
    asm volatile("cp.async.cg.shared.global [%0], [%1], 16;" :: "r"(dst), "l"(src) : "memory");
}
__device__ __forceinline__ void ldmx4(uint32_t* r, uint32_t addr) {
    asm volatile("ldmatrix.sync.aligned.m8n8.x4.shared.b16 {%0,%1,%2,%3}, [%4];"
                 : "=r"(r[0]), "=r"(r[1]), "=r"(r[2]), "=r"(r[3]) : "r"(addr));
}
__device__ __forceinline__ void mma_f16(float* c, const uint32_t* a, uint32_t b0, uint32_t b1) {
    asm volatile(
        "mma.sync.aligned.m16n8k16.row.col.f32.f16.f16.f32 "
        "{%0,%1,%2,%3}, {%4,%5,%6,%7}, {%8,%9}, {%0,%1,%2,%3};"
        : "+f"(c[0]), "+f"(c[1]), "+f"(c[2]), "+f"(c[3])
        : "r"(a[0]), "r"(a[1]), "r"(a[2]), "r"(a[3]), "r"(b0), "r"(b1));
}

// ---------------------------------------------------------------------------
// Pass 0a: q,k -> fp16 hi/mid concatenated arrays + row sum-of-squares
// (full grid: 2*BATCH*LQ blocks, 160 threads, float4)
// ---------------------------------------------------------------------------
__global__ __launch_bounds__(160)
void conv_qk_kernel(const float* __restrict__ q, const float* __restrict__ k) {
    int row = blockIdx.x;
    bool isQ = row < BATCH * LQ;
    int r = isQ ? row : row - BATCH * LQ;
    const float4* src = (const float4*)((isQ ? q : k) + (size_t)r * DIM);
    __half* dst = (isQ ? g_qcat : g_kcat) + (size_t)r * 2 * DIM;

    int t = threadIdx.x;
    float4 x4 = src[t];
    float xs[4] = {x4.x, x4.y, x4.z, x4.w};
    float s = 0.f;
    __half2 hi2[2], mid2[2];
#pragma unroll
    for (int u = 0; u < 2; u++) {
        float a = xs[u * 2], bb = xs[u * 2 + 1];
        s = fmaf(a, a, s);
        s = fmaf(bb, bb, s);
        __half ha = __float2half(a), hb = __float2half(bb);
        float fa = __half2float(ha), fb = __half2float(hb);
        float ma = (fa + (a - fa) * 1024.0f) * 0.03125f;
        float mb = (fb + (bb - fb) * 1024.0f) * 0.03125f;
        hi2[u] = __halves2half2(ha, hb);
        mid2[u] = __halves2half2(__float2half(ma), __float2half(mb));
    }
    *(__half2*)(dst + t * 4) = hi2[0];
    *(__half2*)(dst + t * 4 + 2) = hi2[1];
    *(__half2*)(dst + DIM + t * 4) = mid2[0];
    *(__half2*)(dst + DIM + t * 4 + 2) = mid2[1];

#pragma unroll
    for (int off = 16; off > 0; off >>= 1)
        s += __shfl_down_sync(0xffffffffu, s, off);
    __shared__ float ws[5];
    if ((t & 31) == 0) ws[t >> 5] = s;
    __syncthreads();
    if (t == 0) {
        float tt = ws[0] + ws[1] + ws[2] + ws[3] + ws[4];
        if (isQ) g_qq[r] = tt; else g_kk[r] = tt;
    }
}

// ---------------------------------------------------------------------------
// Pass 0b: v -> transposed fp16: g_v16[(b*DIM+d)*LK + k]
// ---------------------------------------------------------------------------
__global__ __launch_bounds__(256)
void conv_v_kernel(const float* __restrict__ v) {
    __shared__ float tile[32][33];
    int b = blockIdx.z;
    int k0 = blockIdx.x * 32;
    int d0 = blockIdx.y * 32;
    int tx = threadIdx.x, ty = threadIdx.y;
#pragma unroll
    for (int i = ty; i < 32; i += 8)
        tile[i][tx] = v[((size_t)b * LK + k0 + i) * DIM + d0 + tx];
    __syncthreads();
#pragma unroll
    for (int i = ty; i < 32; i += 8) {
        float x = tile[tx][i];  // v[k0+tx][d0+i]
        g_v16[((size_t)b * DIM + d0 + i) * LK + k0 + tx] = __float2half(x);
    }
}

// ---------------------------------------------------------------------------
// mma.sync fp16 GEMM (per batch). CTA tile MT x NT, warps 64x64.
// NPASS=2: merged split (pass0 hi*hi, boundary acc*=(1-2^-10), pass1 e*mid*mid)
// NPASS=1: plain fp16.
// LOGITS: C = (2*acc - qq[m] - kk[n]) / 13.
// ---------------------------------------------------------------------------
template <int MT, int NT, int KDIM, int NPASS, bool LOGITS, int BROWS, int NSTAGE>
__global__ __launch_bounds__((MT / 64) * (NT / 64) * 32, 256 / ((MT / 64) * (NT / 64) * 32))
void gemm_mma_kernel(const uint16_t* __restrict__ Ag,
                     const uint16_t* __restrict__ Bg,
                     float* __restrict__ C, int ldc, int batch) {
    constexpr int WM = MT / 64;
    constexpr int WN = NT / 64;
    constexpr int NTHR = WM * WN * 32;
    constexpr int STRIDE = NPASS * KDIM;
    constexpr int KCH = KDIM / 32;
    constexpr int NCH = NPASS * KCH;
    constexpr int ABYTES = MT * 64;
    constexpr int BBYTES = NT * 64;

    extern __shared__ char dsm[];
    const uint32_t uA = smem_u32(dsm);
    const uint32_t uB = uA + NSTAGE * ABYTES;

    int t = threadIdx.x;
    int wid = t >> 5, lane = t & 31;
    int warp_m = wid % WM;
    int warp_n = wid / WM;
    int b = batch;
    int m0 = blockIdx.y * MT;
    int n0 = blockIdx.x * NT;
    size_t arow0 = (size_t)b * LQ + m0;
    size_t brow0 = (size_t)b * BROWS + n0;

    auto load_chunk = [&](int ck, int st) {
        int pass = ck / KCH;
        int kc = (ck - pass * KCH) * 32;
        int off = (pass == 1) ? KDIM : 0;
        const uint16_t* ab = Ag + arow0 * STRIDE + off + kc;
        const uint16_t* bb = Bg + brow0 * STRIDE + off + kc;
#pragma unroll
        for (int p = t; p < MT * 4; p += NTHR) {
            int row = p >> 2, c = p & 3;
            int cs = c ^ ((row >> 1) & 3);
            cp16(uA + st * ABYTES + row * 64 + cs * 16, ab + (size_t)row * STRIDE + c * 8);
        }
#pragma unroll
        for (int p = t; p < NT * 4; p += NTHR) {
            int row = p >> 2, c = p & 3;
            int cs = c ^ ((row >> 1) & 3);
            cp16(uB + st * BBYTES + row * 64 + cs * 16, bb + (size_t)row * STRIDE + c * 8);
        }
    };

    float acc[4][8][4];
#pragma unroll
    for (int i = 0; i < 4; i++)
#pragma unroll
        for (int j = 0; j < 8; j++)
#pragma unroll
            for (int u = 0; u < 4; u++) acc[i][j][u] = 0.f;

#pragma unroll
    for (int s = 0; s < NSTAGE - 1; s++) {
        if (s < NCH) load_chunk(s, s);
        asm volatile("cp.async.commit_group;" ::: "memory");
    }

    int lr16 = lane & 15;
    int hi16 = lane >> 4;

    for (int s = 0; s < NCH; s++) {
        int pf = s + NSTAGE - 1;
        if (pf < NCH) load_chunk(pf, pf % NSTAGE);
        asm volatile("cp.async.commit_group;" ::: "memory");
        asm volatile("cp.async.wait_group %0;" :: "n"(NSTAGE - 1) : "memory");
        __syncthreads();

        if (NPASS == 2 && s == KCH) {
#pragma unroll
            for (int i = 0; i < 4; i++)
#pragma unroll
                for (int j = 0; j < 8; j++)
#pragma unroll
                    for (int u = 0; u < 4; u++)
                        acc[i][j][u] *= 0.9990234375f;   // 1 - 2^-10
        }

        int st = s % NSTAGE;
        uint32_t aBase = uA + st * ABYTES;
        uint32_t bBase = uB + st * BBYTES;
#pragma unroll
        for (int ks = 0; ks < 2; ks++) {
            int c = ks * 2 + hi16;
            uint32_t afr[4][4];
#pragma unroll
            for (int mt = 0; mt < 4; mt++) {
                int row = warp_m * 64 + mt * 16 + lr16;
                int cs = c ^ ((row >> 1) & 3);
                ldmx4(afr[mt], aBase + row * 64 + cs * 16);
            }
            uint32_t bfr[4][4];
#pragma unroll
            for (int np = 0; np < 4; np++) {
                int row = warp_n * 64 + np * 16 + lr16;
                int cs = c ^ ((row >> 1) & 3);
                ldmx4(bfr[np], bBase + row * 64 + cs * 16);
            }
#pragma unroll
            for (int mt = 0; mt < 4; mt++)
#pragma unroll
                for (int nt = 0; nt < 8; nt++) {
                    int np = nt >> 1, sel = nt & 1;
                    mma_f16(acc[mt][nt], afr[mt], bfr[np][sel], bfr[np][sel + 2]);
                }
        }
        __syncthreads();
    }

    int lr = lane >> 2;
    int lc = (lane & 3) * 2;
#pragma unroll
    for (int mt = 0; mt < 4; mt++) {
#pragma unroll
        for (int h = 0; h < 2; h++) {
            int row = m0 + warp_m * 64 + mt * 16 + h * 8 + lr;
            size_t crow = (size_t)b * LQ + row;
            float qqv = LOGITS ? g_qq[crow] : 0.f;
            float* cp = C + crow * ldc + n0 + warp_n * 64 + lc;
#pragma unroll
            for (int nt = 0; nt < 8; nt++) {
                float v0 = acc[mt][nt][h * 2 + 0];
                float v1 = acc[mt][nt][h * 2 + 1];
                if (LOGITS) {
                    int col = b * LK + n0 + warp_n * 64 + nt * 8 + lc;
                    v0 = (2.f * v0 - qqv - g_kk[col]) * INV_TEMP;
                    v1 = (2.f * v1 - qqv - g_kk[col + 1]) * INV_TEMP;
                }
                float2 w; w.x = v0; w.y = v1;
                *(float2*)(cp + nt * 8) = w;
            }
        }
    }
}

// ---------------------------------------------------------------------------
// Pass 3 (per batch): row softmax; rewrites log_attn in place, writes attn
// fp32 and attn fp16 (g_a16). Proven strided-scalar layout.
// ---------------------------------------------------------------------------
__global__ __launch_bounds__(256)
void softmax_kernel(float* __restrict__ logattn, float* __restrict__ attn,
                    int batch) {
    size_t row = (size_t)batch * LQ + blockIdx.x;
    float* lp = logattn + row * LK;
    float* ap = attn + row * LK;
    __half* a16 = g_a16 + row * (size_t)LK;
    int t = threadIdx.x;

    float x[8];
#pragma unroll
    for (int j = 0; j < 8; j++) x[j] = lp[t + j * 256];

    float m = x[0];
#pragma unroll
    for (int j = 1; j < 8; j++) m = fmaxf(m, x[j]);
#pragma unroll
    for (int off = 16; off > 0; off >>= 1)
        m = fmaxf(m, __shfl_xor_sync(0xffffffffu, m, off));
    __shared__ float red[8];
    __shared__ float bval;
    if ((t & 31) == 0) red[t >> 5] = m;
    __syncthreads();
    if (t == 0) {
        float mm = red[0];
#pragma unroll
        for (int w = 1; w < 8; w++) mm = fmaxf(mm, red[w]);
        bval = mm;
    }
    __syncthreads();
    m = bval;

    float s = 0.f;
#pragma unroll
    for (int j = 0; j < 8; j++) s += expf(x[j] - m);
#pragma unroll
    for (int off = 16; off > 0; off >>= 1)
        s += __shfl_xor_sync(0xffffffffu, s, off);
    __syncthreads();
    if ((t & 31) == 0) red[t >> 5] = s;
    __syncthreads();
    if (t == 0) {
        float ss = 0.f;
#pragma unroll
        for (int w = 0; w < 8; w++) ss += red[w];
        bval = m + logf(ss);
    }
    __syncthreads();
    float lse = bval;

#pragma unroll
    for (int j = 0; j < 8; j++) {
        int idx = t + j * 256;
        float la = x[j] - lse;
        float a = expf(la);
        lp[idx] = la;
        ap[idx] = a;
        a16[idx] = __float2half(a);
    }
}

// ---------------------------------------------------------------------------
extern "C" void kernel_launch(void* const* d_in, const int* in_sizes, int n_in,
                              void* d_out, int out_size) {
    const float* q = (const float*)d_in[0];
    const float* k = (const float*)d_in[1];
    const float* v = (const float*)d_in[2];

    float* out = (float*)d_out;                            // (B, Lq, D)
    float* attn = out + (size_t)BATCH * LQ * DIM;          // (B, Lq, Lk)
    float* logattn = attn + (size_t)BATCH * LQ * LK;       // (B, Lq, Lk)

    // GEMM1: 128x256, 8 warps, 4 stages, fp16 merged 2-pass: smem = 96KB
    constexpr int SM1 = 4 * (128 * 64 + 256 * 64);
    // GEMM2: 64x128, 2 warps, 4 stages, fp16 1-pass: smem = 48KB
    constexpr int SM2 = 4 * (64 * 64 + 128 * 64);

    auto* k1 = gemm_mma_kernel<128, 256, DIM, 2, true, LK, 4>;
    auto* k2 = gemm_mma_kernel<64, 128, LK, 1, false, DIM, 4>;
    cudaFuncSetAttribute(k1, cudaFuncAttributeMaxDynamicSharedMemorySize, SM1);
    cudaFuncSetAttribute(k2, cudaFuncAttributeMaxDynamicSharedMemorySize, SM2);

    // ONE side stream (proven allocation-clean in R11/R12) + events (free).
    static cudaStream_t s2 = nullptr;
    static cudaEvent_t evFork = nullptr, evJoin = nullptr, e1[BATCH];
    if (s2 == nullptr) {
        cudaStreamCreateWithFlags(&s2, cudaStreamNonBlocking);
        cudaEventCreateWithFlags(&evFork, cudaEventDisableTiming);
        cudaEventCreateWithFlags(&evJoin, cudaEventDisableTiming);
        for (int i = 0; i < BATCH; i++)
            cudaEventCreateWithFlags(&e1[i], cudaEventDisableTiming);
    }

    uint16_t* qc; cudaGetSymbolAddress((void**)&qc, g_qcat);
    uint16_t* kc; cudaGetSymbolAddress((void**)&kc, g_kcat);
    uint16_t* ac; cudaGetSymbolAddress((void**)&ac, g_a16);
    uint16_t* vt; cudaGetSymbolAddress((void**)&vt, g_v16);

    // Fork: side stream starts with conv_v (feeds only GEMM2).
    cudaEventRecord(evFork, 0);
    cudaStreamWaitEvent(s2, evFork, 0);
    {
        dim3 g(LK / 32, DIM / 32, BATCH);
        conv_v_kernel<<<g, dim3(32, 8), 0, s2>>>(v);
    }

    // Main stream: conv_qk, then per-batch GEMM1 with completion events.
    conv_qk_kernel<<<2 * BATCH * LQ, 160>>>(q, k);
    for (int b = 0; b < BATCH; b++) {
        dim3 g1(LK / 256, LQ / 128, 1);
        k1<<<g1, 256, SM1>>>(qc, kc, logattn, LK, b);
        cudaEventRecord(e1[b], 0);
    }

    // Side stream: per-batch softmax -> GEMM2, pipelined against GEMM1.
    for (int b = 0; b < BATCH; b++) {
        cudaStreamWaitEvent(s2, e1[b], 0);
        softmax_kernel<<<LQ, 256, 0, s2>>>(logattn, attn, b);
        dim3 g2(DIM / 128, LQ / 64, 1);
        k2<<<g2, 64, SM2, s2>>>(ac, vt, out, DIM, b);
    }
    cudaEventRecord(evJoin, s2);

    // Join: capture stream completes only after the side chain.
    cudaStreamWaitEvent(0, evJoin, 0);
}

// round 16
// speedup vs baseline: 1.1452x; 1.1452x over previous
#include <cuda_runtime.h>
#include <cuda_bf16.h>
#include <cuda_fp16.h>
#include <math.h>
#include <stdint.h>

#define BATCH 8
#define LQ 2048
#define LK 2048
#define DIM 640
#define INV_TEMP (1.0f / 13.0f)

// ---------------------------------------------------------------------------
// Device scratch (allocation-free rule: __device__ globals)
// GEMM1 operands (fp16 merged split, e = 2^-10):
//   row layout [hi(0:DIM) | mid(DIM:2*DIM)]
// GEMM2 operands: plain fp16 (attn, v^T)
// ---------------------------------------------------------------------------
__device__ float g_qq[BATCH * LQ];
__device__ float g_kk[BATCH * LK];
__device__ __half g_qcat[(size_t)BATCH * LQ * 2 * DIM];   // [B*LQ, 1280]
__device__ __half g_kcat[(size_t)BATCH * LK * 2 * DIM];   // [B*LK, 1280]
__device__ __half g_v16[(size_t)BATCH * DIM * LK];        // [B*DIM, 2048] (v^T fp16)
__device__ __half g_a16[(size_t)BATCH * LQ * LK];         // [B*LQ, 2048] (attn fp16)

// ---------------------------------------------------------------------------
// helpers
// ---------------------------------------------------------------------------
__device__ __forceinline__ uint32_t smem_u32(const void* p) {
    uint32_t a;
    asm("{ .reg .u64 t; cvta.to.shared.u64 t, %1; cvt.u32.u64 %0, t; }" : "=r"(a) : "l"(p));
    return a;
}
__device__ __forceinline__ void cp16(uint32_t dst, const void* src) {
    asm volatile("cp.async.cg.shared.global [%0], [%1], 16;" :: "r"(dst), "l"(src) : "memory");
}
__device__ __forceinline__ void ldmx4(uint32_t* r, uint32_t addr) {
    asm volatile("ldmatrix.sync.aligned.m8n8.x4.shared.b16 {%0,%1,%2,%3}, [%4];"
                 : "=r"(r[0]), "=r"(r[1]), "=r"(r[2]), "=r"(r[3]) : "r"(addr));
}
__device__ __forceinline__ void mma_f16(float* c, const uint32_t* a, uint32_t b0, uint32_t b1) {
    asm volatile(
        "mma.sync.aligned.m16n8k16.row.col.f32.f16.f16.f32 "
        "{%0,%1,%2,%3}, {%4,%5,%6,%7}, {%8,%9}, {%0,%1,%2,%3};"
        : "+f"(c[0]), "+f"(c[1]), "+f"(c[2]), "+f"(c[3])
        : "r"(a[0]), "r"(a[1]), "r"(a[2]), "r"(a[3]), "r"(b0), "r"(b1));
}

// ---------------------------------------------------------------------------
// Pass 0a: q,k -> fp16 hi/mid concatenated arrays + row sum-of-squares
// ---------------------------------------------------------------------------
__global__ __launch_bounds__(160)
void conv_qk_kernel(const float* __restrict__ q, const float* __restrict__ k) {
    int row = blockIdx.x;
    bool isQ = row < BATCH * LQ;
    int r = isQ ? row : row - BATCH * LQ;
    const float4* src = (const float4*)((isQ ? q : k) + (size_t)r * DIM);
    __half* dst = (isQ ? g_qcat : g_kcat) + (size_t)r * 2 * DIM;

    int t = threadIdx.x;
    float4 x4 = src[t];
    float xs[4] = {x4.x, x4.y, x4.z, x4.w};
    float s = 0.f;
    __half2 hi2[2], mid2[2];
#pragma unroll
    for (int u = 0; u < 2; u++) {
        float a = xs[u * 2], bb = xs[u * 2 + 1];
        s = fmaf(a, a, s);
        s = fmaf(bb, bb, s);
        __half ha = __float2half(a), hb = __float2half(bb);
        float fa = __half2float(ha), fb = __half2float(hb);
        float ma = (fa + (a - fa) * 1024.0f) * 0.03125f;
        float mb = (fb + (bb - fb) * 1024.0f) * 0.03125f;
        hi2[u] = __halves2half2(ha, hb);
        mid2[u] = __halves2half2(__float2half(ma), __float2half(mb));
    }
    *(__half2*)(dst + t * 4) = hi2[0];
    *(__half2*)(dst + t * 4 + 2) = hi2[1];
    *(__half2*)(dst + DIM + t * 4) = mid2[0];
    *(__half2*)(dst + DIM + t * 4 + 2) = mid2[1];

#pragma unroll
    for (int off = 16; off > 0; off >>= 1)
        s += __shfl_down_sync(0xffffffffu, s, off);
    __shared__ float ws[5];
    if ((t & 31) == 0) ws[t >> 5] = s;
    __syncthreads();
    if (t == 0) {
        float tt = ws[0] + ws[1] + ws[2] + ws[3] + ws[4];
        if (isQ) g_qq[r] = tt; else g_kk[r] = tt;
    }
}

// ---------------------------------------------------------------------------
// Pass 0b: v -> transposed fp16: g_v16[(b*DIM+d)*LK + k]
// ---------------------------------------------------------------------------
__global__ __launch_bounds__(256)
void conv_v_kernel(const float* __restrict__ v) {
    __shared__ float tile[32][33];
    int b = blockIdx.z;
    int k0 = blockIdx.x * 32;
    int d0 = blockIdx.y * 32;
    int tx = threadIdx.x, ty = threadIdx.y;
#pragma unroll
    for (int i = ty; i < 32; i += 8)
        tile[i][tx] = v[((size_t)b * LK + k0 + i) * DIM + d0 + tx];
    __syncthreads();
#pragma unroll
    for (int i = ty; i < 32; i += 8) {
        float x = tile[tx][i];  // v[k0+tx][d0+i]
        g_v16[((size_t)b * DIM + d0 + i) * LK + k0 + tx] = __float2half(x);
    }
}

// ---------------------------------------------------------------------------
// mma.sync fp16 GEMM. CTA tile MT x NT, warp tile 64x32 (occupancy-optimized:
// acc=64 regs -> ~120 regs/thread -> 16 warps/SM).
// Warps laid out (MT/64) x (NT/32).
// NPASS=2: merged split (pass0 hi*hi, boundary acc*=(1-2^-10), pass1 e*mid*mid)
// NPASS=1: plain fp16.
// LOGITS: C = (2*acc - qq[m] - kk[n]) / 13.
// ---------------------------------------------------------------------------
template <int MT, int NT, int KDIM, int NPASS, bool LOGITS, int BROWS, int NSTAGE, int MINB>
__global__ __launch_bounds__((MT / 64) * (NT / 32) * 32, MINB)
void gemm_mma_kernel(const uint16_t* __restrict__ Ag,
                     const uint16_t* __restrict__ Bg,
                     float* __restrict__ C, int ldc) {
    constexpr int WM = MT / 64;
    constexpr int WN = NT / 32;
    constexpr int NTHR = WM * WN * 32;
    constexpr int STRIDE = NPASS * KDIM;
    constexpr int KCH = KDIM / 32;
    constexpr int NCH = NPASS * KCH;
    constexpr int ABYTES = MT * 64;
    constexpr int BBYTES = NT * 64;

    extern __shared__ char dsm[];
    const uint32_t uA = smem_u32(dsm);
    const uint32_t uB = uA + NSTAGE * ABYTES;

    int t = threadIdx.x;
    int wid = t >> 5, lane = t & 31;
    int warp_m = wid % WM;
    int warp_n = wid / WM;
    int b = blockIdx.z;
    int m0 = blockIdx.y * MT;
    int n0 = blockIdx.x * NT;
    size_t arow0 = (size_t)b * LQ + m0;
    size_t brow0 = (size_t)b * BROWS + n0;

    auto load_chunk = [&](int ck, int st) {
        int pass = ck / KCH;
        int kc = (ck - pass * KCH) * 32;
        int off = (pass == 1) ? KDIM : 0;
        const uint16_t* ab = Ag + arow0 * STRIDE + off + kc;
        const uint16_t* bb = Bg + brow0 * STRIDE + off + kc;
#pragma unroll
        for (int p = t; p < MT * 4; p += NTHR) {
            int row = p >> 2, c = p & 3;
            int cs = c ^ ((row >> 1) & 3);
            cp16(uA + st * ABYTES + row * 64 + cs * 16, ab + (size_t)row * STRIDE + c * 8);
        }
#pragma unroll
        for (int p = t; p < NT * 4; p += NTHR) {
            int row = p >> 2, c = p & 3;
            int cs = c ^ ((row >> 1) & 3);
            cp16(uB + st * BBYTES + row * 64 + cs * 16, bb + (size_t)row * STRIDE + c * 8);
        }
    };

    float acc[4][4][4];
#pragma unroll
    for (int i = 0; i < 4; i++)
#pragma unroll
        for (int j = 0; j < 4; j++)
#pragma unroll
            for (int u = 0; u < 4; u++) acc[i][j][u] = 0.f;

#pragma unroll
    for (int s = 0; s < NSTAGE - 1; s++) {
        if (s < NCH) load_chunk(s, s);
        asm volatile("cp.async.commit_group;" ::: "memory");
    }

    int lr16 = lane & 15;
    int hi16 = lane >> 4;

    for (int s = 0; s < NCH; s++) {
        int pf = s + NSTAGE - 1;
        if (pf < NCH) load_chunk(pf, pf % NSTAGE);
        asm volatile("cp.async.commit_group;" ::: "memory");
        asm volatile("cp.async.wait_group %0;" :: "n"(NSTAGE - 1) : "memory");
        __syncthreads();

        if (NPASS == 2 && s == KCH) {
#pragma unroll
            for (int i = 0; i < 4; i++)
#pragma unroll
                for (int j = 0; j < 4; j++)
#pragma unroll
                    for (int u = 0; u < 4; u++)
                        acc[i][j][u] *= 0.9990234375f;   // 1 - 2^-10
        }

        int st = s % NSTAGE;
        uint32_t aBase = uA + st * ABYTES;
        uint32_t bBase = uB + st * BBYTES;
#pragma unroll
        for (int ks = 0; ks < 2; ks++) {
            int c = ks * 2 + hi16;
            uint32_t afr[4][4];
#pragma unroll
            for (int mt = 0; mt < 4; mt++) {
                int row = warp_m * 64 + mt * 16 + lr16;
                int cs = c ^ ((row >> 1) & 3);
                ldmx4(afr[mt], aBase + row * 64 + cs * 16);
            }
            uint32_t bfr[2][4];
#pragma unroll
            for (int np = 0; np < 2; np++) {
                int row = warp_n * 32 + np * 16 + lr16;
                int cs = c ^ ((row >> 1) & 3);
                ldmx4(bfr[np], bBase + row * 64 + cs * 16);
            }
#pragma unroll
            for (int mt = 0; mt < 4; mt++)
#pragma unroll
                for (int nt = 0; nt < 4; nt++) {
                    int np = nt >> 1, sel = nt & 1;
                    mma_f16(acc[mt][nt], afr[mt], bfr[np][sel], bfr[np][sel + 2]);
                }
        }
        __syncthreads();
    }

    int lr = lane >> 2;
    int lc = (lane & 3) * 2;
#pragma unroll
    for (int mt = 0; mt < 4; mt++) {
#pragma unroll
        for (int h = 0; h < 2; h++) {
            int row = m0 + warp_m * 64 + mt * 16 + h * 8 + lr;
            size_t crow = (size_t)b * LQ + row;
            float qqv = LOGITS ? g_qq[crow] : 0.f;
            float* cp = C + crow * ldc + n0 + warp_n * 32 + lc;
#pragma unroll
            for (int nt = 0; nt < 4; nt++) {
                float v0 = acc[mt][nt][h * 2 + 0];
                float v1 = acc[mt][nt][h * 2 + 1];
                if (LOGITS) {
                    int col = b * LK + n0 + warp_n * 32 + nt * 8 + lc;
                    v0 = (2.f * v0 - qqv - g_kk[col]) * INV_TEMP;
                    v1 = (2.f * v1 - qqv - g_kk[col + 1]) * INV_TEMP;
                }
                float2 w; w.x = v0; w.y = v1;
                *(float2*)(cp + nt * 8) = w;
            }
        }
    }
}

// ---------------------------------------------------------------------------
// Pass 3: row softmax (proven strided-scalar layout); rewrites log_attn in
// place, writes attn fp32 and attn fp16 (g_a16).
// ---------------------------------------------------------------------------
__global__ __launch_bounds__(256)
void softmax_kernel(float* __restrict__ logattn, float* __restrict__ attn) {
    size_t row = blockIdx.x;
    float* lp = logattn + row * LK;
    float* ap = attn + row * LK;
    __half* a16 = g_a16 + row * (size_t)LK;
    int t = threadIdx.x;

    float x[8];
#pragma unroll
    for (int j = 0; j < 8; j++) x[j] = lp[t + j * 256];

    float m = x[0];
#pragma unroll
    for (int j = 1; j < 8; j++) m = fmaxf(m, x[j]);
#pragma unroll
    for (int off = 16; off > 0; off >>= 1)
        m = fmaxf(m, __shfl_xor_sync(0xffffffffu, m, off));
    __shared__ float red[8];
    __shared__ float bval;
    if ((t & 31) == 0) red[t >> 5] = m;
    __syncthreads();
    if (t == 0) {
        float mm = red[0];
#pragma unroll
        for (int w = 1; w < 8; w++) mm = fmaxf(mm, red[w]);
        bval = mm;
    }
    __syncthreads();
    m = bval;

    float s = 0.f;
#pragma unroll
    for (int j = 0; j < 8; j++) s += expf(x[j] - m);
#pragma unroll
    for (int off = 16; off > 0; off >>= 1)
        s += __shfl_xor_sync(0xffffffffu, s, off);
    __syncthreads();
    if ((t & 31) == 0) red[t >> 5] = s;
    __syncthreads();
    if (t == 0) {
        float ss = 0.f;
#pragma unroll
        for (int w = 0; w < 8; w++) ss += red[w];
        bval = m + logf(ss);
    }
    __syncthreads();
    float lse = bval;

#pragma unroll
    for (int j = 0; j < 8; j++) {
        int idx = t + j * 256;
        float la = x[j] - lse;
        float a = expf(la);
        lp[idx] = la;
        ap[idx] = a;
        a16[idx] = __float2half(a);
    }
}

// ---------------------------------------------------------------------------
extern "C" void kernel_launch(void* const* d_in, const int* in_sizes, int n_in,
                              void* d_out, int out_size) {
    const float* q = (const float*)d_in[0];
    const float* k = (const float*)d_in[1];
    const float* v = (const float*)d_in[2];

    float* out = (float*)d_out;                            // (B, Lq, D)
    float* attn = out + (size_t)BATCH * LQ * DIM;          // (B, Lq, Lk)
    float* logattn = attn + (size_t)BATCH * LQ * LK;       // (B, Lq, Lk)

    // GEMM1: 128x256, 16 warps (64x32 tiles), 4 stages: smem = 96KB, 1 CTA/SM
    constexpr int SM1 = 4 * (128 * 64 + 256 * 64);
    // GEMM2: 128x128, 8 warps (64x32 tiles), 3 stages: smem = 48KB, 2 CTAs/SM
    constexpr int SM2 = 3 * (128 * 64 + 128 * 64);

    auto* k1 = gemm_mma_kernel<128, 256, DIM, 2, true, LK, 4, 1>;
    auto* k2 = gemm_mma_kernel<128, 128, LK, 1, false, DIM, 3, 2>;
    cudaFuncSetAttribute(k1, cudaFuncAttributeMaxDynamicSharedMemorySize, SM1);
    cudaFuncSetAttribute(k2, cudaFuncAttributeMaxDynamicSharedMemorySize, SM2);

    // ONE side stream (proven allocation-clean) + events.
    static cudaStream_t s2 = nullptr;
    static cudaEvent_t evFork = nullptr, evJoin = nullptr;
    if (s2 == nullptr) {
        cudaStreamCreateWithFlags(&s2, cudaStreamNonBlocking);
        cudaEventCreateWithFlags(&evFork, cudaEventDisableTiming);
        cudaEventCreateWithFlags(&evJoin, cudaEventDisableTiming);
    }

    uint16_t* qc; cudaGetSymbolAddress((void**)&qc, g_qcat);
    uint16_t* kc; cudaGetSymbolAddress((void**)&kc, g_kcat);
    uint16_t* ac; cudaGetSymbolAddress((void**)&ac, g_a16);
    uint16_t* vt; cudaGetSymbolAddress((void**)&vt, g_v16);

    // Fork: conv_v overlaps the conv_qk -> GEMM1 -> softmax chain.
    cudaEventRecord(evFork, 0);
    cudaStreamWaitEvent(s2, evFork, 0);
    {
        dim3 g(LK / 32, DIM / 32, BATCH);
        conv_v_kernel<<<g, dim3(32, 8), 0, s2>>>(v);
    }
    cudaEventRecord(evJoin, s2);

    // Main chain
    conv_qk_kernel<<<2 * BATCH * LQ, 160>>>(q, k);

    // Pass 1: logits (into log_attn region)
    {
        dim3 g(LK / 256, LQ / 128, BATCH);
        k1<<<g, 512, SM1>>>(qc, kc, logattn, LK);
    }

    // Pass 2: softmax (in-place log_attn, attn fp32, attn fp16)
    softmax_kernel<<<BATCH * LQ, 256>>>(logattn, attn);

    // Join: GEMM2 needs g_v16 from conv_v
    cudaStreamWaitEvent(0, evJoin, 0);

    // Pass 3: out = attn @ V
    {
        dim3 g(DIM / 128, LQ / 128, BATCH);
        k2<<<g, 256, SM2>>>(ac, vt, out, DIM);
    }
}